// round 7
// baseline (speedup 1.0000x reference)
#include <cuda_runtime.h>
#include <float.h>

// Problem constants (fixed by setup_inputs)
#define Bv 4
#define Nv 16384
#define Dv 512
#define Sv 512
#define Mv (Bv * Nv)       // 65536 rows for fx/gx GEMM
#define MYv (Bv * Sv)      // 2048 rows for hy GEMM

// ---------------- scratch (device globals; no runtime allocation) ----------
__device__ float g_fx[(size_t)Mv * Dv];     // [B,N,D] 128 MiB
__device__ float g_gx[(size_t)Mv * Dv];     // [B,N,D] 128 MiB
__device__ float g_y [(size_t)MYv * Dv];    // [B,S,D] 4 MiB
__device__ float g_hy[(size_t)MYv * Dv];    // [B,S,D] 4 MiB
__device__ int   g_segstart[Sv + 1];

// ---------------- K0: segment boundaries from sorted jx (int32!) -----------
__global__ void seg_bounds_kernel(const int* __restrict__ jx) {
    int n = blockIdx.x * blockDim.x + threadIdx.x;
    if (n > Nv) return;
    int cur  = (n < Nv) ? min(max(jx[n], 0), Sv - 1)     : Sv;
    int prev = (n > 0)  ? min(max(jx[n - 1], 0), Sv - 1) : -1;
    for (int s = prev + 1; s <= cur; ++s) g_segstart[s] = n;
}

// ---------------- K1/K3: tiled SGEMM  out[m,e] = sum_d A[m,d]*W[e,d] + b[e]
// A: [M,K] row-major, W: [Nout,K] row-major (both K-contiguous).
// A == nullptr  -> use device-global g_y as the A operand (K3).
// out_sel: 0 -> g_fx, 1 -> g_gx, 2 -> g_hy.
#define BM 128
#define BN 128
#define BK 16
__global__ __launch_bounds__(256, 2)
void sgemm_nt_kernel(const float* __restrict__ A_in, const float* __restrict__ W,
                     const float* __restrict__ bias, int out_sel,
                     int M, int K, int Nout) {
    const float* A = (A_in != nullptr) ? A_in : g_y;
    float* out = (out_sel == 0) ? g_fx : (out_sel == 1) ? g_gx : g_hy;

    __shared__ float As[BK][BM];
    __shared__ float Ws[BK][BN];
    const int bm = blockIdx.y * BM;
    const int bn = blockIdx.x * BN;
    const int tid = threadIdx.x;
    const int tr = tid >> 4;     // 0..15 -> row group of 8
    const int tc = tid & 15;     // 0..15 -> col group of 8

    float acc[8][8];
#pragma unroll
    for (int i = 0; i < 8; ++i)
#pragma unroll
        for (int j = 0; j < 8; ++j) acc[i][j] = 0.f;

    for (int k0 = 0; k0 < K; k0 += BK) {
        // load A tile (128 x 16) transposed into smem
#pragma unroll
        for (int q = tid; q < BM * BK / 4; q += 256) {
            int row = q >> 2, c4 = (q & 3) * 4;
            float4 v = *reinterpret_cast<const float4*>(
                &A[(size_t)(bm + row) * K + k0 + c4]);
            As[c4 + 0][row] = v.x; As[c4 + 1][row] = v.y;
            As[c4 + 2][row] = v.z; As[c4 + 3][row] = v.w;
        }
        // load W tile (128 x 16) transposed into smem
#pragma unroll
        for (int q = tid; q < BN * BK / 4; q += 256) {
            int row = q >> 2, c4 = (q & 3) * 4;
            float4 v = *reinterpret_cast<const float4*>(
                &W[(size_t)(bn + row) * K + k0 + c4]);
            Ws[c4 + 0][row] = v.x; Ws[c4 + 1][row] = v.y;
            Ws[c4 + 2][row] = v.z; Ws[c4 + 3][row] = v.w;
        }
        __syncthreads();

#pragma unroll
        for (int kk = 0; kk < BK; ++kk) {
            float4 a0 = *reinterpret_cast<const float4*>(&As[kk][tr * 8]);
            float4 a1 = *reinterpret_cast<const float4*>(&As[kk][tr * 8 + 4]);
            float4 w0 = *reinterpret_cast<const float4*>(&Ws[kk][tc * 8]);
            float4 w1 = *reinterpret_cast<const float4*>(&Ws[kk][tc * 8 + 4]);
            float a[8] = {a0.x, a0.y, a0.z, a0.w, a1.x, a1.y, a1.z, a1.w};
            float w[8] = {w0.x, w0.y, w0.z, w0.w, w1.x, w1.y, w1.z, w1.w};
#pragma unroll
            for (int i = 0; i < 8; ++i)
#pragma unroll
                for (int j = 0; j < 8; ++j) acc[i][j] += a[i] * w[j];
        }
        __syncthreads();
    }

    // epilogue: add bias, store
    const int col0 = bn + tc * 8;
    float bb[8];
#pragma unroll
    for (int j = 0; j < 8; ++j) bb[j] = bias[col0 + j];
    const int row0 = bm + tr * 8;
#pragma unroll
    for (int i = 0; i < 8; ++i) {
        float4 o0, o1;
        o0.x = acc[i][0] + bb[0]; o0.y = acc[i][1] + bb[1];
        o0.z = acc[i][2] + bb[2]; o0.w = acc[i][3] + bb[3];
        o1.x = acc[i][4] + bb[4]; o1.y = acc[i][5] + bb[5];
        o1.z = acc[i][6] + bb[6]; o1.w = acc[i][7] + bb[7];
        float* po = &out[(size_t)(row0 + i) * Nout + col0];
        *reinterpret_cast<float4*>(po)     = o0;
        *reinterpret_cast<float4*>(po + 4) = o1;
    }
}

// ---------------- K2: fused segment softmax + weighted scatter-sum ---------
// one block per (s, b); segment rows are contiguous [segstart[s], segstart[s+1])
__global__ void segsoftagg_kernel() {
    const int s = blockIdx.x;
    const int b = blockIdx.y;
    const int n0 = g_segstart[s];
    const int n1 = g_segstart[s + 1];
    const int d = threadIdx.x * 4;

    float4 yv = make_float4(0.f, 0.f, 0.f, 0.f);
    if (n1 > n0) {
        // pass 1: segment max (per channel)
        float4 mv = make_float4(-FLT_MAX, -FLT_MAX, -FLT_MAX, -FLT_MAX);
        const size_t base_b = (size_t)b * Nv * Dv;
        for (int n = n0; n < n1; ++n) {
            float4 g = *reinterpret_cast<const float4*>(&g_gx[base_b + (size_t)n * Dv + d]);
            mv.x = fmaxf(mv.x, g.x); mv.y = fmaxf(mv.y, g.y);
            mv.z = fmaxf(mv.z, g.z); mv.w = fmaxf(mv.w, g.w);
        }
        // pass 2: exp / accumulate numerator & denominator
        float4 num = make_float4(0.f, 0.f, 0.f, 0.f);
        float4 den = make_float4(0.f, 0.f, 0.f, 0.f);
        for (int n = n0; n < n1; ++n) {
            size_t off = base_b + (size_t)n * Dv + d;
            float4 g = *reinterpret_cast<const float4*>(&g_gx[off]);
            float4 f = *reinterpret_cast<const float4*>(&g_fx[off]);
            float ex = __expf(g.x - mv.x), ey = __expf(g.y - mv.y);
            float ez = __expf(g.z - mv.z), ew = __expf(g.w - mv.w);
            den.x += ex; den.y += ey; den.z += ez; den.w += ew;
            num.x += ex * f.x; num.y += ey * f.y;
            num.z += ez * f.z; num.w += ew * f.w;
        }
        yv.x = num.x / den.x; yv.y = num.y / den.y;
        yv.z = num.z / den.z; yv.w = num.w / den.w;
    }
    *reinterpret_cast<float4*>(&g_y[((size_t)b * Sv + s) * Dv + d]) = yv;
}

// ---------------- K4: gather out[b,n,:] = hy[b, jx[n], :] (jx int32!) ------
__global__ void gather_kernel(const int* __restrict__ jx,
                              float* __restrict__ out) {
    int idx = blockIdx.x * blockDim.x + threadIdx.x;   // float4 index
    if (idx >= Bv * Nv * (Dv / 4)) return;
    int d4  = idx & (Dv / 4 - 1);
    int bn  = idx >> 7;            // D/4 = 128
    int n   = bn & (Nv - 1);
    int b   = bn >> 14;            // N = 16384
    int s   = min(max(jx[n], 0), Sv - 1);
    const float4* hy4 = reinterpret_cast<const float4*>(g_hy);
    reinterpret_cast<float4*>(out)[idx] = hy4[((size_t)(b * Sv + s)) * (Dv / 4) + d4];
}

// ---------------- host launcher --------------------------------------------
extern "C" void kernel_launch(void* const* d_in, const int* in_sizes, int n_in,
                              void* d_out, int out_size) {
    // Locate inputs by element count (robust to scalar num_segments presence)
    const float* x = nullptr;
    const int* jx = nullptr;
    const float *Wf = nullptr, *bf = nullptr, *Wg = nullptr, *bg = nullptr,
                *Wh = nullptr, *bh = nullptr;
    int wcnt = 0, bcnt = 0;
    for (int i = 0; i < n_in; ++i) {
        int sz = in_sizes[i];
        if (sz == Bv * Nv * Dv) {
            x = (const float*)d_in[i];
        } else if (sz == Nv) {
            jx = (const int*)d_in[i];
        } else if (sz == Dv * Dv) {
            if (wcnt == 0) Wf = (const float*)d_in[i];
            else if (wcnt == 1) Wg = (const float*)d_in[i];
            else Wh = (const float*)d_in[i];
            ++wcnt;
        } else if (sz == Dv) {
            if (bcnt == 0) bf = (const float*)d_in[i];
            else if (bcnt == 1) bg = (const float*)d_in[i];
            else bh = (const float*)d_in[i];
            ++bcnt;
        }
        // size-1 scalar (num_segments) ignored: S fixed at 512
    }

    // K0: segment boundaries
    seg_bounds_kernel<<<(Nv + 1 + 255) / 256, 256>>>(jx);

    // K1: fx = x @ Wf^T + bf ; gx = x @ Wg^T + bg   (outputs g_fx / g_gx)
    dim3 g1(Dv / BN, Mv / BM);
    sgemm_nt_kernel<<<g1, 256>>>(x, Wf, bf, /*out_sel=*/0, Mv, Dv, Dv);
    sgemm_nt_kernel<<<g1, 256>>>(x, Wg, bg, /*out_sel=*/1, Mv, Dv, Dv);

    // K2: segment softmax + weighted sum -> g_y [B,S,D]
    dim3 g2(Sv, Bv);
    segsoftagg_kernel<<<g2, Dv / 4>>>();

    // K3: hy = y @ Wh^T + bh  (A = g_y via nullptr, output g_hy)
    dim3 g3(Dv / BN, MYv / BM);
    sgemm_nt_kernel<<<g3, 256>>>(nullptr, Wh, bh, /*out_sel=*/2, MYv, Dv, Dv);

    // K4: gather back to [B,N,D]
    int total4 = Bv * Nv * (Dv / 4);
    gather_kernel<<<(total4 + 255) / 256, 256>>>(jx, (float*)d_out);
}

// round 13
// speedup vs baseline: 1.9539x; 1.9539x over previous
#include <cuda_runtime.h>
#include <cuda_bf16.h>
#include <float.h>
#include <cstdint>

// Problem constants (fixed by setup_inputs)
#define Bv 4
#define Nv 16384
#define Dv 512
#define Sv 512
#define Mv (Bv * Nv)       // 65536 rows for fx/gx GEMM
#define MYv (Bv * Sv)      // 2048 rows for hy GEMM

// ---------------- scratch (device globals; no runtime allocation) ----------
__device__ float g_fx[(size_t)Mv * Dv];     // [B,N,D] 128 MiB
__device__ float g_gx[(size_t)Mv * Dv];     // [B,N,D] 128 MiB
__device__ float g_y [(size_t)MYv * Dv];    // [B,S,D] 4 MiB
__device__ float g_hy[(size_t)MYv * Dv];    // [B,S,D] 4 MiB
__device__ int   g_segstart[Sv + 1];

// ---------------- helpers ---------------------------------------------------
__device__ __forceinline__ uint32_t smem_to_u32(const void* p) {
    uint32_t a;
    asm("{ .reg .u64 t; cvta.to.shared.u64 t, %1; cvt.u32.u64 %0, t; }"
        : "=r"(a) : "l"(p));
    return a;
}
__device__ __forceinline__ void ldm_x4(uint32_t* r, uint32_t addr) {
    asm volatile("ldmatrix.sync.aligned.m8n8.x4.shared.b16 {%0,%1,%2,%3}, [%4];"
        : "=r"(r[0]), "=r"(r[1]), "=r"(r[2]), "=r"(r[3]) : "r"(addr));
}
__device__ __forceinline__ void mma_bf16(float* c, const uint32_t* a,
                                         uint32_t b0, uint32_t b1) {
    asm volatile(
        "mma.sync.aligned.m16n8k16.row.col.f32.bf16.bf16.f32 "
        "{%0,%1,%2,%3}, {%4,%5,%6,%7}, {%8,%9}, {%0,%1,%2,%3};"
        : "+f"(c[0]), "+f"(c[1]), "+f"(c[2]), "+f"(c[3])
        : "r"(a[0]), "r"(a[1]), "r"(a[2]), "r"(a[3]), "r"(b0), "r"(b1));
}

// ---------------- K0: segment boundaries from sorted jx (int32) ------------
__global__ void seg_bounds_kernel(const int* __restrict__ jx) {
    int n = blockIdx.x * blockDim.x + threadIdx.x;
    if (n > Nv) return;
    int cur  = (n < Nv) ? min(max(jx[n], 0), Sv - 1)     : Sv;
    int prev = (n > 0)  ? min(max(jx[n - 1], 0), Sv - 1) : -1;
    for (int s = prev + 1; s <= cur; ++s) g_segstart[s] = n;
}

// ---------------- K1/K3: bf16 hi/lo split mma GEMM --------------------------
// out[m,e] = sum_d A[m,d]*W[e,d] + bias[e]
// A row-major [M,512], W row-major [512,512] (both K-contiguous).
// A_in == nullptr -> g_y. out_sel: 0->g_fx, 1->g_gx, 2->g_hy.
// CTA tile 128x128, 8 warps (2m x 4n of 64x32 warp tiles), BK=16, dbl-buffered.
#define TBK 16
#define ROWB 48                 // smem bytes per 16-bf16 row (pad: conflict-free)
#define TILEB (128 * ROWB)      // 6144 B per matrix tile
#define BUFB (4 * TILEB)        // A_hi, A_lo, B_hi, B_lo
#define SMTOT (2 * BUFB)        // 49152 B

__global__ __launch_bounds__(256, 1)
void mma_gemm_kernel(const float* __restrict__ A_in, const float* __restrict__ W,
                     const float* __restrict__ bias, int out_sel, int M) {
    extern __shared__ char sm[];
    const float* A = (A_in != nullptr) ? A_in : g_y;
    float* out = (out_sel == 0) ? g_fx : (out_sel == 1) ? g_gx : g_hy;

    const int tid = threadIdx.x;
    const int wid = tid >> 5, lane = tid & 31;
    const int bm = blockIdx.y * 128, bn = blockIdx.x * 128;
    const int wm = (wid >> 2) * 64, wn = (wid & 3) * 32;
    const uint32_t sbase = smem_to_u32(sm);

    // per-thread staging: row tid>>1 (0..127), cols (tid&1)*8 .. +7
    const int lrow = tid >> 1;
    const int lcol = (tid & 1) * 8;
    const float* gA = &A[(size_t)(bm + lrow) * Dv + lcol];
    const float* gW = &W[(size_t)(bn + lrow) * Dv + lcol];
    const uint32_t sts_off = (uint32_t)(lrow * ROWB + lcol * 2);

    float sa[8], sb[8];
    auto ldg = [&](int k0) {
        float4 v0 = *reinterpret_cast<const float4*>(gA + k0);
        float4 v1 = *reinterpret_cast<const float4*>(gA + k0 + 4);
        sa[0]=v0.x; sa[1]=v0.y; sa[2]=v0.z; sa[3]=v0.w;
        sa[4]=v1.x; sa[5]=v1.y; sa[6]=v1.z; sa[7]=v1.w;
        float4 w0 = *reinterpret_cast<const float4*>(gW + k0);
        float4 w1 = *reinterpret_cast<const float4*>(gW + k0 + 4);
        sb[0]=w0.x; sb[1]=w0.y; sb[2]=w0.z; sb[3]=w0.w;
        sb[4]=w1.x; sb[5]=w1.y; sb[6]=w1.z; sb[7]=w1.w;
    };
    auto sts = [&](int buf) {
        union { __nv_bfloat16 h[8]; uint4 u; } ahi, alo, bhi, blo;
#pragma unroll
        for (int j = 0; j < 8; ++j) {
            __nv_bfloat16 h = __float2bfloat16(sa[j]);
            ahi.h[j] = h;
            alo.h[j] = __float2bfloat16(sa[j] - __bfloat162float(h));
            __nv_bfloat16 g = __float2bfloat16(sb[j]);
            bhi.h[j] = g;
            blo.h[j] = __float2bfloat16(sb[j] - __bfloat162float(g));
        }
        char* base = sm + buf * BUFB + sts_off;
        *reinterpret_cast<uint4*>(base)             = ahi.u;
        *reinterpret_cast<uint4*>(base + TILEB)     = alo.u;
        *reinterpret_cast<uint4*>(base + 2 * TILEB) = bhi.u;
        *reinterpret_cast<uint4*>(base + 3 * TILEB) = blo.u;
    };

    float acc[4][4][4];
#pragma unroll
    for (int i = 0; i < 4; ++i)
#pragma unroll
        for (int j = 0; j < 4; ++j)
#pragma unroll
            for (int q = 0; q < 4; ++q) acc[i][j][q] = 0.f;

    // ldmatrix per-lane address pieces
    const int lrow16 = lane & 15;
    const int ksel   = (lane >> 4) * 8;     // 0 or 8 (bf16 elements)

    ldg(0);
    sts(0);
    __syncthreads();

    for (int ch = 0; ch < Dv / TBK; ++ch) {
        if (ch < Dv / TBK - 1) ldg((ch + 1) * TBK);

        const uint32_t abase = sbase + (ch & 1) * BUFB;
        uint32_t a_hi[4][4], a_lo[4][4], bh[2][4], bl[2][4];
#pragma unroll
        for (int mi = 0; mi < 4; ++mi) {
            uint32_t ra = abase + (uint32_t)((wm + mi * 16 + lrow16) * ROWB + ksel * 2);
            ldm_x4(a_hi[mi], ra);
            ldm_x4(a_lo[mi], ra + TILEB);
        }
#pragma unroll
        for (int h = 0; h < 2; ++h) {
            uint32_t rb = abase + 2 * TILEB +
                          (uint32_t)((wn + h * 16 + lrow16) * ROWB + ksel * 2);
            ldm_x4(bh[h], rb);
            ldm_x4(bl[h], rb + TILEB);
        }
#pragma unroll
        for (int mi = 0; mi < 4; ++mi)
#pragma unroll
            for (int ni = 0; ni < 4; ++ni) {
                const int g = ni >> 1, s = ni & 1;
                mma_bf16(acc[mi][ni], a_hi[mi], bh[g][s], bh[g][s + 2]);
                mma_bf16(acc[mi][ni], a_hi[mi], bl[g][s], bl[g][s + 2]);
                mma_bf16(acc[mi][ni], a_lo[mi], bh[g][s], bh[g][s + 2]);
            }

        if (ch < Dv / TBK - 1) sts((ch + 1) & 1);
        __syncthreads();
    }

    // epilogue: c0=(r,c), c1=(r,c+1), c2=(r+8,c), c3=(r+8,c+1); r=lane/4, c=2*(lane%4)
#pragma unroll
    for (int ni = 0; ni < 4; ++ni) {
        const int col = bn + wn + ni * 8 + (lane & 3) * 2;
        const float b0 = bias[col], b1 = bias[col + 1];
#pragma unroll
        for (int mi = 0; mi < 4; ++mi) {
            const int row = bm + wm + mi * 16 + (lane >> 2);
            float2 v0 = make_float2(acc[mi][ni][0] + b0, acc[mi][ni][1] + b1);
            float2 v1 = make_float2(acc[mi][ni][2] + b0, acc[mi][ni][3] + b1);
            *reinterpret_cast<float2*>(&out[(size_t)row * Dv + col]) = v0;
            *reinterpret_cast<float2*>(&out[(size_t)(row + 8) * Dv + col]) = v1;
        }
    }
}

// ---------------- K2: fused segment softmax + weighted scatter-sum ---------
__global__ void segsoftagg_kernel() {
    const int s = blockIdx.x;
    const int b = blockIdx.y;
    const int n0 = g_segstart[s];
    const int n1 = g_segstart[s + 1];
    const int d = threadIdx.x * 4;

    float4 yv = make_float4(0.f, 0.f, 0.f, 0.f);
    if (n1 > n0) {
        float4 mv = make_float4(-FLT_MAX, -FLT_MAX, -FLT_MAX, -FLT_MAX);
        const size_t base_b = (size_t)b * Nv * Dv;
        for (int n = n0; n < n1; ++n) {
            float4 g = *reinterpret_cast<const float4*>(&g_gx[base_b + (size_t)n * Dv + d]);
            mv.x = fmaxf(mv.x, g.x); mv.y = fmaxf(mv.y, g.y);
            mv.z = fmaxf(mv.z, g.z); mv.w = fmaxf(mv.w, g.w);
        }
        float4 num = make_float4(0.f, 0.f, 0.f, 0.f);
        float4 den = make_float4(0.f, 0.f, 0.f, 0.f);
        for (int n = n0; n < n1; ++n) {
            size_t off = base_b + (size_t)n * Dv + d;
            float4 g = *reinterpret_cast<const float4*>(&g_gx[off]);
            float4 f = *reinterpret_cast<const float4*>(&g_fx[off]);
            float ex = __expf(g.x - mv.x), ey = __expf(g.y - mv.y);
            float ez = __expf(g.z - mv.z), ew = __expf(g.w - mv.w);
            den.x += ex; den.y += ey; den.z += ez; den.w += ew;
            num.x += ex * f.x; num.y += ey * f.y;
            num.z += ez * f.z; num.w += ew * f.w;
        }
        yv.x = num.x / den.x; yv.y = num.y / den.y;
        yv.z = num.z / den.z; yv.w = num.w / den.w;
    }
    *reinterpret_cast<float4*>(&g_y[((size_t)b * Sv + s) * Dv + d]) = yv;
}

// ---------------- K4: gather out[b,n,:] = hy[b, jx[n], :] ------------------
__global__ void gather_kernel(const int* __restrict__ jx,
                              float* __restrict__ out) {
    int idx = blockIdx.x * blockDim.x + threadIdx.x;   // float4 index
    if (idx >= Bv * Nv * (Dv / 4)) return;
    int d4  = idx & (Dv / 4 - 1);
    int bn  = idx >> 7;            // D/4 = 128
    int n   = bn & (Nv - 1);
    int b   = bn >> 14;            // N = 16384
    int s   = min(max(jx[n], 0), Sv - 1);
    const float4* hy4 = reinterpret_cast<const float4*>(g_hy);
    reinterpret_cast<float4*>(out)[idx] = hy4[((size_t)(b * Sv + s)) * (Dv / 4) + d4];
}

// ---------------- host launcher --------------------------------------------
extern "C" void kernel_launch(void* const* d_in, const int* in_sizes, int n_in,
                              void* d_out, int out_size) {
    const float* x = nullptr;
    const int* jx = nullptr;
    const float *Wf = nullptr, *bf = nullptr, *Wg = nullptr, *bg = nullptr,
                *Wh = nullptr, *bh = nullptr;
    int wcnt = 0, bcnt = 0;
    for (int i = 0; i < n_in; ++i) {
        int sz = in_sizes[i];
        if (sz == Bv * Nv * Dv) {
            x = (const float*)d_in[i];
        } else if (sz == Nv) {
            jx = (const int*)d_in[i];
        } else if (sz == Dv * Dv) {
            if (wcnt == 0) Wf = (const float*)d_in[i];
            else if (wcnt == 1) Wg = (const float*)d_in[i];
            else Wh = (const float*)d_in[i];
            ++wcnt;
        } else if (sz == Dv) {
            if (bcnt == 0) bf = (const float*)d_in[i];
            else if (bcnt == 1) bg = (const float*)d_in[i];
            else bh = (const float*)d_in[i];
            ++bcnt;
        }
    }

    // K0: segment boundaries
    seg_bounds_kernel<<<(Nv + 1 + 255) / 256, 256>>>(jx);

    // K1: fx, gx via bf16-split mma GEMM
    cudaFuncSetAttribute(mma_gemm_kernel,
                         cudaFuncAttributeMaxDynamicSharedMemorySize, SMTOT);
    dim3 g1(Dv / 128, Mv / 128);
    mma_gemm_kernel<<<g1, 256, SMTOT>>>(x, Wf, bf, /*out_sel=*/0, Mv);
    mma_gemm_kernel<<<g1, 256, SMTOT>>>(x, Wg, bg, /*out_sel=*/1, Mv);

    // K2: segment softmax + weighted sum -> g_y [B,S,D]
    dim3 g2(Sv, Bv);
    segsoftagg_kernel<<<g2, Dv / 4>>>();

    // K3: hy = y @ Wh^T + bh
    dim3 g3(Dv / 128, MYv / 128);
    mma_gemm_kernel<<<g3, 256, SMTOT>>>(nullptr, Wh, bh, /*out_sel=*/2, MYv);

    // K4: gather back to [B,N,D]
    int total4 = Bv * Nv * (Dv / 4);
    gather_kernel<<<(total4 + 255) / 256, 256>>>(jx, (float*)d_out);
}